// round 2
// baseline (speedup 1.0000x reference)
#include <cuda_runtime.h>

// Problem constants (from reference)
#define B_  128
#define T_  32
#define D_  512
#define N4_ (B_ * T_ * D_ / 4)   // 524288 float4
#define D4_ (D_ / 4)             // 128

#define NBLK 512
#define NTHR 256
#define NTH  (NBLK * NTHR)       // 131072 threads; N4_/NTH == 4 exactly

// Persistent accumulators. Invariant: zero at kernel entry.
__device__ float    g_acc[2] = {0.f, 0.f};
__device__ unsigned g_count  = 0u;

// out layout: [0]=sl_rhat [1]=sl_rbar [2]=temp_loss=0 [3]=r2_losses=0
//             [4..4+B*R)=r0 zeros, then r2 zeros.
__global__ void __launch_bounds__(NTHR)
tidhy_reduce_kernel(const float4* __restrict__ X4,
                    const float4* __restrict__ bsd4,
                    float* __restrict__ out,
                    int out_size)
{
    const int tid = blockIdx.x * NTHR + threadIdx.x;

    // ---- zero-fill out[2 .. out_size): vectorized on [4, ...) ----
    {
        const float4 z4 = make_float4(0.f, 0.f, 0.f, 0.f);
        float4* out4 = (float4*)(out + 4);          // byte offset 16: aligned
        const int n4 = (out_size - 4) >> 2;         // tail handled below
        for (int i = tid; i < n4; i += NTH) out4[i] = z4;
        if (tid == 0) {
            out[2] = 0.f; out[3] = 0.f;
            for (int i = 4 + (n4 << 2); i < out_size; ++i) out[i] = 0.f;
        }
    }

    // ---- front-batched loads: 4 float4 per thread, stride NTH ----
    // stride NTH = 131072 is a multiple of D4_*T_ = 4096, so for all 4 loads:
    //   d-index (float4) = tid & 127        -> single b_sd load
    //   timestep t       = (tid >> 7) & 31  -> single predicate
    const float4 x0 = X4[tid];
    const float4 x1 = X4[tid +     NTH];
    const float4 x2 = X4[tid + 2 * NTH];
    const float4 x3 = X4[tid + 3 * NTH];
    const float4 b  = bsd4[tid & (D4_ - 1)];

    float v;
    {
        float d0x = x0.x - b.x, d0y = x0.y - b.y, d0z = x0.z - b.z, d0w = x0.w - b.w;
        float d1x = x1.x - b.x, d1y = x1.y - b.y, d1z = x1.z - b.z, d1w = x1.w - b.w;
        float d2x = x2.x - b.x, d2y = x2.y - b.y, d2z = x2.z - b.z, d2w = x2.w - b.w;
        float d3x = x3.x - b.x, d3y = x3.y - b.y, d3z = x3.z - b.z, d3w = x3.w - b.w;
        float v0 = d0x*d0x + d0y*d0y + d0z*d0z + d0w*d0w;
        float v1 = d1x*d1x + d1y*d1y + d1z*d1z + d1w*d1w;
        float v2 = d2x*d2x + d2y*d2y + d2z*d2z + d2w*d2w;
        float v3 = d3x*d3x + d3y*d3y + d3z*d3z + d3w*d3w;
        v = (v0 + v1) + (v2 + v3);
    }

    const bool is_t0 = (((tid >> 7) & (T_ - 1)) == 0);
    float s_all = v;
    float s_t0  = is_t0 ? v : 0.f;

    // ---- intra-block reduction ----
    #pragma unroll
    for (int o = 16; o > 0; o >>= 1) {
        s_all += __shfl_xor_sync(0xffffffffu, s_all, o);
        s_t0  += __shfl_xor_sync(0xffffffffu, s_t0,  o);
    }
    __shared__ float sh_a[8], sh_t[8];
    const int lane = threadIdx.x & 31;
    const int wid  = threadIdx.x >> 5;
    if (lane == 0) { sh_a[wid] = s_all; sh_t[wid] = s_t0; }
    __syncthreads();

    if (wid == 0) {
        float a = (lane < (NTHR >> 5)) ? sh_a[lane] : 0.f;
        float t = (lane < (NTHR >> 5)) ? sh_t[lane] : 0.f;
        #pragma unroll
        for (int o = 4; o > 0; o >>= 1) {
            a += __shfl_xor_sync(0xffffffffu, a, o);
            t += __shfl_xor_sync(0xffffffffu, t, o);
        }
        if (lane == 0) {
            atomicAdd(&g_acc[0], a);          // sum over all t
            atomicAdd(&g_acc[1], a - t);      // sum over t >= 1
            __threadfence();
            unsigned old = atomicInc(&g_count, NBLK - 1);  // wraps to 0
            if (old == NBLK - 1) {
                // atomicExch = coherent read + reset (zero-invariant per replay)
                float tot_all = atomicExch(&g_acc[0], 0.f);
                float tot_r   = atomicExch(&g_acc[1], 0.f);
                out[0] = tot_all * (1.0f / (float)B_);  // sl_rhat
                out[1] = tot_r   * (1.0f / (float)B_);  // sl_rbar
            }
        }
    }
}

extern "C" void kernel_launch(void* const* d_in, const int* in_sizes, int n_in,
                              void* d_out, int out_size)
{
    const float4* X4   = (const float4*)d_in[0];
    const float4* bsd4 = (const float4*)d_in[3];
    float* out = (float*)d_out;
    tidhy_reduce_kernel<<<NBLK, NTHR>>>(X4, bsd4, out, out_size);
}